// round 1
// baseline (speedup 1.0000x reference)
#include <cuda_runtime.h>
#include <cstdint>

// ---------------------------------------------------------------------------
// GraphConvolutionLayer: out = segment_sum(vals[e] * (x@W)[src[e]] -> dst[e]) + bias
//   x:        [N, 128] f32
//   weight:   [128, 64] f32
//   bias:     [64] f32
//   edge_src: [E] i32
//   edge_dst: [E] i32
//   edge_vals:[E] f32
//   out:      [N, 64] f32
// ---------------------------------------------------------------------------

#define IN_F  128
#define OUT_F 64
#define MAX_NODES 100000

// scratch for support = x @ W  (allocation-free rule: __device__ global)
__device__ float g_support[(size_t)MAX_NODES * OUT_F];

// ---------------------------------------------------------------------------
// Kernel 1: out[i][j] = bias[j]   (vectorized float4; 16 float4 per row)
// ---------------------------------------------------------------------------
__global__ void init_out_kernel(const float* __restrict__ bias,
                                float* __restrict__ out, int total4) {
    int t = blockIdx.x * blockDim.x + threadIdx.x;
    if (t >= total4) return;
    int j4 = (t & 15);  // 64/4 = 16 float4 per row
    float4 b = reinterpret_cast<const float4*>(bias)[j4];
    reinterpret_cast<float4*>(out)[t] = b;
}

// ---------------------------------------------------------------------------
// Kernel 2: tiled fp32 GEMM  support[M,64] = x[M,128] @ W[128,64]
//   BM=128 BN=64 BK=16, 256 threads, per-thread tile 8(M) x 4(N)
// ---------------------------------------------------------------------------
#define BM 128
#define BN 64
#define BK 16

__global__ __launch_bounds__(256)
void gemm_kernel(const float* __restrict__ A,   // [M,128]
                 const float* __restrict__ W,   // [128,64]
                 float* __restrict__ C,         // [M,64]
                 int M) {
    __shared__ float As[BK][BM];   // transposed A tile
    __shared__ float Bs[BK][BN];

    int tid = threadIdx.x;
    int rowBase = blockIdx.x * BM;

    int ty = tid >> 4;        // 0..15  -> M groups of 8
    int tx = tid & 15;        // 0..15  -> N groups of 4

    float4 acc[8];
    #pragma unroll
    for (int i = 0; i < 8; i++) acc[i] = make_float4(0.f, 0.f, 0.f, 0.f);

    for (int kBase = 0; kBase < IN_F; kBase += BK) {
        // --- load A tile: 128 rows x 16 cols = 512 float4, 2 per thread ---
        #pragma unroll
        for (int i = 0; i < 2; i++) {
            int idx = tid + i * 256;          // 0..511
            int row = idx >> 2;               // 0..127
            int c4  = idx & 3;                // 0..3  (4 float4 per row-slice)
            int grow = rowBase + row;
            float4 v = make_float4(0.f, 0.f, 0.f, 0.f);
            if (grow < M)
                v = *reinterpret_cast<const float4*>(A + (size_t)grow * IN_F + kBase + c4 * 4);
            As[c4 * 4 + 0][row] = v.x;
            As[c4 * 4 + 1][row] = v.y;
            As[c4 * 4 + 2][row] = v.z;
            As[c4 * 4 + 3][row] = v.w;
        }
        // --- load B tile: 16 rows x 64 cols = 256 float4, 1 per thread ---
        {
            int row = tid >> 4;   // 0..15
            int c4  = tid & 15;   // 0..15
            float4 v = *reinterpret_cast<const float4*>(W + (size_t)(kBase + row) * OUT_F + c4 * 4);
            *reinterpret_cast<float4*>(&Bs[row][c4 * 4]) = v;
        }
        __syncthreads();

        #pragma unroll
        for (int k = 0; k < BK; k++) {
            float4 a0 = *reinterpret_cast<const float4*>(&As[k][ty * 8 + 0]);
            float4 a1 = *reinterpret_cast<const float4*>(&As[k][ty * 8 + 4]);
            float4 b  = *reinterpret_cast<const float4*>(&Bs[k][tx * 4]);
            float am[8] = {a0.x, a0.y, a0.z, a0.w, a1.x, a1.y, a1.z, a1.w};
            #pragma unroll
            for (int m = 0; m < 8; m++) {
                acc[m].x += am[m] * b.x;
                acc[m].y += am[m] * b.y;
                acc[m].z += am[m] * b.z;
                acc[m].w += am[m] * b.w;
            }
        }
        __syncthreads();
    }

    #pragma unroll
    for (int m = 0; m < 8; m++) {
        int grow = rowBase + ty * 8 + m;
        if (grow < M)
            *reinterpret_cast<float4*>(C + (size_t)grow * OUT_F + tx * 4) = acc[m];
    }
}

// ---------------------------------------------------------------------------
// Kernel 3: scatter — 16 lanes per edge, one float4 per lane, vector RED
// ---------------------------------------------------------------------------
__global__ void scatter_kernel(const int*   __restrict__ src,
                               const int*   __restrict__ dst,
                               const float* __restrict__ vals,
                               const float* __restrict__ support,
                               float*       __restrict__ out,
                               int nE) {
    int t = blockIdx.x * blockDim.x + threadIdx.x;
    int e = t >> 4;
    if (e >= nE) return;
    int j = (t & 15) << 2;             // 0,4,...,60

    int   s = __ldg(&src[e]);
    int   d = __ldg(&dst[e]);
    float v = __ldg(&vals[e]);

    float4 sv = *reinterpret_cast<const float4*>(support + (size_t)s * OUT_F + j);
    float4 m  = make_float4(sv.x * v, sv.y * v, sv.z * v, sv.w * v);

    float* p = out + (size_t)d * OUT_F + j;
    asm volatile("red.global.add.v4.f32 [%0], {%1,%2,%3,%4};"
                 :: "l"(p), "f"(m.x), "f"(m.y), "f"(m.z), "f"(m.w)
                 : "memory");
}

// ---------------------------------------------------------------------------
extern "C" void kernel_launch(void* const* d_in, const int* in_sizes, int n_in,
                              void* d_out, int out_size) {
    const float* x        = (const float*)d_in[0];
    const float* weight   = (const float*)d_in[1];
    const float* bias     = (const float*)d_in[2];
    const int*   edge_src = (const int*)  d_in[3];
    const int*   edge_dst = (const int*)  d_in[4];
    const float* edge_val = (const float*)d_in[5];
    float* out = (float*)d_out;

    int M  = in_sizes[0] / IN_F;      // number of nodes
    int nE = in_sizes[3];             // number of edges

    float* support;
    cudaGetSymbolAddress((void**)&support, g_support);

    // 1) out = bias (broadcast)
    {
        int total4 = M * (OUT_F / 4);
        int threads = 256;
        int blocks = (total4 + threads - 1) / threads;
        init_out_kernel<<<blocks, threads>>>(bias, out, total4);
    }
    // 2) support = x @ W
    {
        int blocks = (M + BM - 1) / BM;
        gemm_kernel<<<blocks, 256>>>(x, weight, support, M);
    }
    // 3) scatter with vector reductions
    {
        long long tasks = (long long)nE * 16;
        int threads = 256;
        long long blocks = (tasks + threads - 1) / threads;
        scatter_kernel<<<(unsigned)blocks, threads>>>(edge_src, edge_dst, edge_val,
                                                      support, out, nE);
    }
}

// round 2
// speedup vs baseline: 1.1946x; 1.1946x over previous
#include <cuda_runtime.h>
#include <cstdint>

// ---------------------------------------------------------------------------
// GraphConvolutionLayer: out = segment_sum(vals[e] * (x@W)[src[e]] -> dst[e]) + bias
// Strategy: bucket edges by dst (counting placement, no scan), then per-dst
// warp gather with register accumulation -> single store per node, no atomics
// in the hot loop.
// ---------------------------------------------------------------------------

#define IN_F  128
#define OUT_F 64
#define MAX_NODES 100000
#define CAP 128              // bucket capacity per dst (Poisson(16) -> never hit)
#define OVF_CAP 65536        // correctness backstop

__device__ float g_support[(size_t)MAX_NODES * OUT_F];
__device__ int   g_count[MAX_NODES];
__device__ int2  g_bucket[(size_t)MAX_NODES * CAP];   // (src, val-as-int)
__device__ int   g_ovf_count;
__device__ int4  g_ovf[OVF_CAP];                      // (src, dst, val, pad)

// ---------------------------------------------------------------------------
// Kernel 1: tiled fp32 GEMM  support[M,64] = x[M,128] @ W[128,64]
// ---------------------------------------------------------------------------
#define BM 128
#define BN 64
#define BK 16

__global__ __launch_bounds__(256)
void gemm_kernel(const float* __restrict__ A,   // [M,128]
                 const float* __restrict__ W,   // [128,64]
                 float* __restrict__ C,         // [M,64]
                 int M) {
    __shared__ float As[BK][BM];   // transposed A tile
    __shared__ float Bs[BK][BN];

    int tid = threadIdx.x;
    int rowBase = blockIdx.x * BM;

    int ty = tid >> 4;        // 0..15  -> M groups of 8
    int tx = tid & 15;        // 0..15  -> N groups of 4

    float4 acc[8];
    #pragma unroll
    for (int i = 0; i < 8; i++) acc[i] = make_float4(0.f, 0.f, 0.f, 0.f);

    for (int kBase = 0; kBase < IN_F; kBase += BK) {
        #pragma unroll
        for (int i = 0; i < 2; i++) {
            int idx = tid + i * 256;          // 0..511
            int row = idx >> 2;               // 0..127
            int c4  = idx & 3;                // 0..3
            int grow = rowBase + row;
            float4 v = make_float4(0.f, 0.f, 0.f, 0.f);
            if (grow < M)
                v = *reinterpret_cast<const float4*>(A + (size_t)grow * IN_F + kBase + c4 * 4);
            As[c4 * 4 + 0][row] = v.x;
            As[c4 * 4 + 1][row] = v.y;
            As[c4 * 4 + 2][row] = v.z;
            As[c4 * 4 + 3][row] = v.w;
        }
        {
            int row = tid >> 4;   // 0..15
            int c4  = tid & 15;   // 0..15
            float4 v = *reinterpret_cast<const float4*>(W + (size_t)(kBase + row) * OUT_F + c4 * 4);
            *reinterpret_cast<float4*>(&Bs[row][c4 * 4]) = v;
        }
        __syncthreads();

        #pragma unroll
        for (int k = 0; k < BK; k++) {
            float4 a0 = *reinterpret_cast<const float4*>(&As[k][ty * 8 + 0]);
            float4 a1 = *reinterpret_cast<const float4*>(&As[k][ty * 8 + 4]);
            float4 b  = *reinterpret_cast<const float4*>(&Bs[k][tx * 4]);
            float am[8] = {a0.x, a0.y, a0.z, a0.w, a1.x, a1.y, a1.z, a1.w};
            #pragma unroll
            for (int m = 0; m < 8; m++) {
                acc[m].x += am[m] * b.x;
                acc[m].y += am[m] * b.y;
                acc[m].z += am[m] * b.z;
                acc[m].w += am[m] * b.w;
            }
        }
        __syncthreads();
    }

    #pragma unroll
    for (int m = 0; m < 8; m++) {
        int grow = rowBase + ty * 8 + m;
        if (grow < M)
            *reinterpret_cast<float4*>(C + (size_t)grow * OUT_F + tx * 4) = acc[m];
    }
}

// ---------------------------------------------------------------------------
// Kernel 2: bucket fill — counting placement by dst
// ---------------------------------------------------------------------------
__global__ void fill_kernel(const int*   __restrict__ src,
                            const int*   __restrict__ dst,
                            const float* __restrict__ vals,
                            int nE) {
    int e = blockIdx.x * blockDim.x + threadIdx.x;
    if (e >= nE) return;
    int   s = __ldg(&src[e]);
    int   d = __ldg(&dst[e]);
    float v = __ldg(&vals[e]);
    int pos = atomicAdd(&g_count[d], 1);
    if (pos < CAP) {
        g_bucket[(size_t)d * CAP + pos] = make_int2(s, __float_as_int(v));
    } else {
        int o = atomicAdd(&g_ovf_count, 1);
        if (o < OVF_CAP) g_ovf[o] = make_int4(s, d, __float_as_int(v), 0);
    }
}

// ---------------------------------------------------------------------------
// Kernel 3: gather — one warp per dst node, register accumulation, one store
// ---------------------------------------------------------------------------
__global__ __launch_bounds__(256)
void gather_kernel(const float* __restrict__ support,
                   const float* __restrict__ bias,
                   float* __restrict__ out, int M) {
    int w    = (blockIdx.x * blockDim.x + threadIdx.x) >> 5;
    int lane = threadIdx.x & 31;
    if (w >= M) return;

    int deg = g_count[w];
    if (deg > CAP) deg = CAP;

    float acc0 = 0.f, acc1 = 0.f;
    const int2* bkt = g_bucket + (size_t)w * CAP;

    #pragma unroll 4
    for (int j = 0; j < deg; j++) {
        int2 pr = __ldg(&bkt[j]);                         // warp-broadcast load
        float v = __int_as_float(pr.y);
        const float* row = support + (size_t)pr.x * OUT_F;
        acc0 += v * __ldg(&row[lane]);
        acc1 += v * __ldg(&row[lane + 32]);
    }

    out[(size_t)w * OUT_F + lane]      = acc0 + __ldg(&bias[lane]);
    out[(size_t)w * OUT_F + 32 + lane] = acc1 + __ldg(&bias[lane + 32]);
}

// ---------------------------------------------------------------------------
// Kernel 4: overflow backstop — vector RED into out (after gather wrote base)
// ---------------------------------------------------------------------------
__global__ void ovf_kernel(const float* __restrict__ support,
                           float* __restrict__ out) {
    int n = g_ovf_count;
    if (n > OVF_CAP) n = OVF_CAP;
    if (n <= 0) return;
    int total = n * 16;
    for (int t = blockIdx.x * blockDim.x + threadIdx.x; t < total;
         t += gridDim.x * blockDim.x) {
        int e = t >> 4;
        int j = (t & 15) << 2;
        int4 r = g_ovf[e];
        float v = __int_as_float(r.z);
        float4 sv = *reinterpret_cast<const float4*>(support + (size_t)r.x * OUT_F + j);
        float4 m  = make_float4(sv.x * v, sv.y * v, sv.z * v, sv.w * v);
        float* p = out + (size_t)r.y * OUT_F + j;
        asm volatile("red.global.add.v4.f32 [%0], {%1,%2,%3,%4};"
                     :: "l"(p), "f"(m.x), "f"(m.y), "f"(m.z), "f"(m.w)
                     : "memory");
    }
}

// ---------------------------------------------------------------------------
extern "C" void kernel_launch(void* const* d_in, const int* in_sizes, int n_in,
                              void* d_out, int out_size) {
    const float* x        = (const float*)d_in[0];
    const float* weight   = (const float*)d_in[1];
    const float* bias     = (const float*)d_in[2];
    const int*   edge_src = (const int*)  d_in[3];
    const int*   edge_dst = (const int*)  d_in[4];
    const float* edge_val = (const float*)d_in[5];
    float* out = (float*)d_out;

    int M  = in_sizes[0] / IN_F;
    int nE = in_sizes[3];

    float* support;  cudaGetSymbolAddress((void**)&support, g_support);
    int*   countp;   cudaGetSymbolAddress((void**)&countp, g_count);
    int*   ovfcp;    cudaGetSymbolAddress((void**)&ovfcp, g_ovf_count);

    // reset counters (graph-capturable async memsets)
    cudaMemsetAsync(countp, 0, (size_t)M * sizeof(int));
    cudaMemsetAsync(ovfcp, 0, sizeof(int));

    // support = x @ W
    gemm_kernel<<<(M + BM - 1) / BM, 256>>>(x, weight, support, M);

    // bucket edges by dst
    fill_kernel<<<(nE + 255) / 256, 256>>>(edge_src, edge_dst, edge_val, nE);

    // per-node gather (+bias), one store per node
    {
        int warps = M;
        int blocks = (warps * 32 + 255) / 256;
        gather_kernel<<<blocks, 256>>>(support, bias, out, M);
    }

    // overflow backstop (no-op in practice)
    ovf_kernel<<<64, 256>>>(support, out);
}

// round 4
// speedup vs baseline: 1.4477x; 1.2118x over previous
#include <cuda_runtime.h>
#include <cuda_fp16.h>
#include <cstdint>

// ---------------------------------------------------------------------------
// GraphConvolutionLayer: out = segment_sum(vals[e] * (x@W)[src[e]] -> dst[e]) + bias
// R3 strategy (resubmit after infra failure):
//   - support stored as fp16 (halves gather L2 traffic; error ~1e-4 << 1e-3)
//   - fill (dst-bucketing) fused into the GEMM grid -> overlap memory w/ FMA
//   - per-dst warp gather, register accumulation, one store per node
// ---------------------------------------------------------------------------

#define IN_F  128
#define OUT_F 64
#define MAX_NODES 100000
#define CAP 128
#define OVF_CAP 65536

__device__ __half g_support[(size_t)MAX_NODES * OUT_F];
__device__ int    g_count[MAX_NODES];
__device__ int2   g_bucket[(size_t)MAX_NODES * CAP];   // (src, val-as-int)
__device__ int    g_ovf_count;
__device__ int4   g_ovf[OVF_CAP];

#define BM 128
#define BN 64
#define BK 16

// ---------------------------------------------------------------------------
// Kernel 1 (fused): blocks [0, nGemm) -> GEMM tile; blocks [nGemm, ...) -> fill
// ---------------------------------------------------------------------------
__global__ __launch_bounds__(256)
void gemm_fill_kernel(const float* __restrict__ A,   // [M,128]
                      const float* __restrict__ W,   // [128,64]
                      __half*      __restrict__ C,   // [M,64] fp16
                      int M, int nGemm,
                      const int*   __restrict__ src,
                      const int*   __restrict__ dst,
                      const float* __restrict__ vals,
                      int nE) {
    if ((int)blockIdx.x >= nGemm) {
        // ---------------- fill part: bucket edges by dst ----------------
        int e = (blockIdx.x - nGemm) * blockDim.x + threadIdx.x;
        if (e >= nE) return;
        int   s = __ldg(&src[e]);
        int   d = __ldg(&dst[e]);
        float v = __ldg(&vals[e]);
        int pos = atomicAdd(&g_count[d], 1);
        if (pos < CAP) {
            g_bucket[(size_t)d * CAP + pos] = make_int2(s, __float_as_int(v));
        } else {
            int o = atomicAdd(&g_ovf_count, 1);
            if (o < OVF_CAP) g_ovf[o] = make_int4(s, d, __float_as_int(v), 0);
        }
        return;
    }

    // ---------------- GEMM part ----------------
    __shared__ float As[BK][BM];   // transposed A tile
    __shared__ float Bs[BK][BN];

    int tid = threadIdx.x;
    int rowBase = blockIdx.x * BM;

    int ty = tid >> 4;        // 0..15
    int tx = tid & 15;        // 0..15

    float4 acc[8];
    #pragma unroll
    for (int i = 0; i < 8; i++) acc[i] = make_float4(0.f, 0.f, 0.f, 0.f);

    for (int kBase = 0; kBase < IN_F; kBase += BK) {
        #pragma unroll
        for (int i = 0; i < 2; i++) {
            int idx = tid + i * 256;
            int row = idx >> 2;
            int c4  = idx & 3;
            int grow = rowBase + row;
            float4 v = make_float4(0.f, 0.f, 0.f, 0.f);
            if (grow < M)
                v = *reinterpret_cast<const float4*>(A + (size_t)grow * IN_F + kBase + c4 * 4);
            As[c4 * 4 + 0][row] = v.x;
            As[c4 * 4 + 1][row] = v.y;
            As[c4 * 4 + 2][row] = v.z;
            As[c4 * 4 + 3][row] = v.w;
        }
        {
            int row = tid >> 4;
            int c4  = tid & 15;
            float4 v = *reinterpret_cast<const float4*>(W + (size_t)(kBase + row) * OUT_F + c4 * 4);
            *reinterpret_cast<float4*>(&Bs[row][c4 * 4]) = v;
        }
        __syncthreads();

        #pragma unroll
        for (int k = 0; k < BK; k++) {
            float4 a0 = *reinterpret_cast<const float4*>(&As[k][ty * 8 + 0]);
            float4 a1 = *reinterpret_cast<const float4*>(&As[k][ty * 8 + 4]);
            float4 b  = *reinterpret_cast<const float4*>(&Bs[k][tx * 4]);
            float am[8] = {a0.x, a0.y, a0.z, a0.w, a1.x, a1.y, a1.z, a1.w};
            #pragma unroll
            for (int m = 0; m < 8; m++) {
                acc[m].x += am[m] * b.x;
                acc[m].y += am[m] * b.y;
                acc[m].z += am[m] * b.z;
                acc[m].w += am[m] * b.w;
            }
        }
        __syncthreads();
    }

    #pragma unroll
    for (int m = 0; m < 8; m++) {
        int grow = rowBase + ty * 8 + m;
        if (grow < M) {
            __half2 h01 = __float22half2_rn(make_float2(acc[m].x, acc[m].y));
            __half2 h23 = __float22half2_rn(make_float2(acc[m].z, acc[m].w));
            uint2 packed = make_uint2(*(uint32_t*)&h01, *(uint32_t*)&h23);
            *reinterpret_cast<uint2*>(C + (size_t)grow * OUT_F + tx * 4) = packed;
        }
    }
}

// ---------------------------------------------------------------------------
// Kernel 2: gather — one warp per dst node; lane owns columns 2*lane, 2*lane+1
// ---------------------------------------------------------------------------
__global__ __launch_bounds__(256)
void gather_kernel(const __half* __restrict__ support,
                   const float*  __restrict__ bias,
                   float* __restrict__ out, int M) {
    int w    = (blockIdx.x * blockDim.x + threadIdx.x) >> 5;
    int lane = threadIdx.x & 31;
    if (w >= M) return;

    int deg = g_count[w];
    if (deg > CAP) deg = CAP;

    float2 acc = make_float2(0.f, 0.f);
    const int2* bkt = g_bucket + (size_t)w * CAP;

    #pragma unroll 4
    for (int j = 0; j < deg; j++) {
        int2 pr = __ldg(&bkt[j]);                          // warp-broadcast
        float v = __int_as_float(pr.y);
        const uint32_t* row = reinterpret_cast<const uint32_t*>(
            support + (size_t)pr.x * OUT_F);
        uint32_t h2raw = __ldg(&row[lane]);                // 2 halfs, coalesced 128B
        float2 f = __half22float2(*reinterpret_cast<__half2*>(&h2raw));
        acc.x += v * f.x;
        acc.y += v * f.y;
    }

    float2 b = __ldg(reinterpret_cast<const float2*>(bias) + lane);
    float2 r = make_float2(acc.x + b.x, acc.y + b.y);
    *reinterpret_cast<float2*>(out + (size_t)w * OUT_F + 2 * lane) = r;
}

// ---------------------------------------------------------------------------
// Kernel 3: overflow backstop (no-op in practice, correctness guarantee)
// ---------------------------------------------------------------------------
__global__ void ovf_kernel(const __half* __restrict__ support,
                           float* __restrict__ out) {
    int n = g_ovf_count;
    if (n > OVF_CAP) n = OVF_CAP;
    if (n <= 0) return;
    int total = n * 16;
    for (int t = blockIdx.x * blockDim.x + threadIdx.x; t < total;
         t += gridDim.x * blockDim.x) {
        int e = t >> 4;
        int j = (t & 15) << 2;                  // column group of 4
        int4 r = g_ovf[e];
        float v = __int_as_float(r.z);
        const uint32_t* row = reinterpret_cast<const uint32_t*>(
            support + (size_t)r.x * OUT_F);
        uint32_t a = __ldg(&row[j >> 1]);
        uint32_t c = __ldg(&row[(j >> 1) + 1]);
        float2 f01 = __half22float2(*reinterpret_cast<__half2*>(&a));
        float2 f23 = __half22float2(*reinterpret_cast<__half2*>(&c));
        float* p = out + (size_t)r.y * OUT_F + j;
        asm volatile("red.global.add.v4.f32 [%0], {%1,%2,%3,%4};"
                     :: "l"(p), "f"(f01.x * v), "f"(f01.y * v),
                        "f"(f23.x * v), "f"(f23.y * v)
                     : "memory");
    }
}

// ---------------------------------------------------------------------------
extern "C" void kernel_launch(void* const* d_in, const int* in_sizes, int n_in,
                              void* d_out, int out_size) {
    const float* x        = (const float*)d_in[0];
    const float* weight   = (const float*)d_in[1];
    const float* bias     = (const float*)d_in[2];
    const int*   edge_src = (const int*)  d_in[3];
    const int*   edge_dst = (const int*)  d_in[4];
    const float* edge_val = (const float*)d_in[5];
    float* out = (float*)d_out;

    int M  = in_sizes[0] / IN_F;
    int nE = in_sizes[3];

    __half* support; cudaGetSymbolAddress((void**)&support, g_support);
    int*    countp;  cudaGetSymbolAddress((void**)&countp, g_count);
    int*    ovfcp;   cudaGetSymbolAddress((void**)&ovfcp, g_ovf_count);

    cudaMemsetAsync(countp, 0, (size_t)M * sizeof(int));
    cudaMemsetAsync(ovfcp, 0, sizeof(int));

    // fused: GEMM tiles + edge bucketing in one grid
    int nGemm = (M + BM - 1) / BM;
    int nFill = (nE + 255) / 256;
    gemm_fill_kernel<<<nGemm + nFill, 256>>>(x, weight, support, M, nGemm,
                                             edge_src, edge_dst, edge_val, nE);

    // per-node gather (+bias), one store per node
    gather_kernel<<<(M * 32 + 255) / 256, 256>>>(support, bias, out, M);

    // overflow backstop
    ovf_kernel<<<64, 256>>>(support, out);
}